// round 6
// baseline (speedup 1.0000x reference)
#include <cuda_runtime.h>
#include <cuda_bf16.h>
#include <cstdint>
#include <cstddef>

// ---------------------------------------------------------------------------
// Scratch (__device__ globals; no cudaMalloc allowed)
// ---------------------------------------------------------------------------
__device__ float g_c[64];
__device__ __align__(16) __nv_bfloat16 g_Mhi[64 * 1024];
__device__ __align__(16) __nv_bfloat16 g_Mlo[64 * 1024];
__device__ int g_cnt[16];   // [0..7]: M chunk counters (target 1024), [8]: c counter (target 64)

#define NUM_CHUNK 8
#define CHUNK     128
#define LDA       136
#define AHI_OFF   0
#define ALO_OFF   17408
#define BHI_OFF   34816
#define BLO_OFF   52224
#define STAGE_BYTES 69632
#define SX2_OFF   0
#define ST0       4096
#define RED_OFF   (ST0 + 2 * STAGE_BYTES)          // 143360
#define SMEM_TOTAL (RED_OFF + 512)                  // 143872

// ---------------------------------------------------------------------------
// Small helpers
// ---------------------------------------------------------------------------
__device__ __forceinline__ int ld_acquire(const int* p) {
    int v;
    asm volatile("ld.acquire.gpu.b32 %0, [%1];" : "=r"(v) : "l"(p) : "memory");
    return v;
}

__device__ __forceinline__ void wait_cnt(const int* c, int target) {
    if ((threadIdx.x & 31) == 0) {
        while (ld_acquire(c) < target) __nanosleep(64);
    }
    __syncwarp();
    ld_acquire(c);   // per-lane acquire so every lane's later loads are ordered
}

#define CBAR() asm volatile("bar.sync 1, 256;" ::: "memory")

__device__ __forceinline__ uint32_t pack_bf16x2(__nv_bfloat16 a, __nv_bfloat16 b) {
    __nv_bfloat162 t; t.x = a; t.y = b;
    return *reinterpret_cast<uint32_t*>(&t);
}

__device__ __forceinline__ void split_pair(float f0, float f1, uint32_t& h, uint32_t& l) {
    __nv_bfloat16 h0 = __float2bfloat16_rn(f0);
    __nv_bfloat16 h1 = __float2bfloat16_rn(f1);
    h = pack_bf16x2(h0, h1);
    l = pack_bf16x2(__float2bfloat16_rn(f0 - __bfloat162float(h0)),
                    __float2bfloat16_rn(f1 - __bfloat162float(h1)));
}

__device__ __forceinline__ void mma16816(float d[4], const uint32_t a[4],
                                         uint32_t b0, uint32_t b1) {
    asm volatile(
        "mma.sync.aligned.m16n8k16.row.col.f32.bf16.bf16.f32 "
        "{%0,%1,%2,%3}, {%4,%5,%6,%7}, {%8,%9}, {%0,%1,%2,%3};"
        : "+f"(d[0]), "+f"(d[1]), "+f"(d[2]), "+f"(d[3])
        : "r"(a[0]), "r"(a[1]), "r"(a[2]), "r"(a[3]), "r"(b0), "r"(b1));
}

// ---------------------------------------------------------------------------
// Consumer pieces (ctid = 0..255)
// ---------------------------------------------------------------------------
__device__ __forceinline__ void ldg_a(const float* __restrict__ x1, int row0, int ch,
                                      int ctid, float4 pa[8]) {
#pragma unroll
    for (int t = 0; t < 8; t++) {
        int g = ctid + t * 256;             // 0..2047
        int r = g >> 5;                     // row 0..63
        int c4 = (g & 31) * 4;              // col 0..124
        pa[t] = *reinterpret_cast<const float4*>(x1 + (size_t)(row0 + r) * 1024 + ch * CHUNK + c4);
    }
}

__device__ __forceinline__ void ldg_b(int ch, int ctid, uint4 pbh[4], uint4 pbl[4]) {
#pragma unroll
    for (int t = 0; t < 4; t++) {
        int g = ctid + t * 256;             // 0..1023
        int n = g >> 4;                     // k_out 0..63
        int k8 = (g & 15) * 8;              // col 0..120
        pbh[t] = *reinterpret_cast<const uint4*>(g_Mhi + (size_t)n * 1024 + ch * CHUNK + k8);
        pbl[t] = *reinterpret_cast<const uint4*>(g_Mlo + (size_t)n * 1024 + ch * CHUNK + k8);
    }
}

__device__ __forceinline__ void sts_chunk(char* stage, int ctid, const float4 pa[8],
                                          const uint4 pbh[4], const uint4 pbl[4]) {
#pragma unroll
    for (int t = 0; t < 8; t++) {
        int g = ctid + t * 256;
        int r = g >> 5;
        int c4 = (g & 31) * 4;
        uint32_t h0, l0, h1, l1;
        split_pair(pa[t].x, pa[t].y, h0, l0);
        split_pair(pa[t].z, pa[t].w, h1, l1);
        int off = (r * LDA + c4) * 2;
        *reinterpret_cast<uint2*>(stage + AHI_OFF + off) = make_uint2(h0, h1);
        *reinterpret_cast<uint2*>(stage + ALO_OFF + off) = make_uint2(l0, l1);
    }
#pragma unroll
    for (int t = 0; t < 4; t++) {
        int g = ctid + t * 256;
        int n = g >> 4;
        int k8 = (g & 15) * 8;
        int off = (n * LDA + k8) * 2;
        *reinterpret_cast<uint4*>(stage + BHI_OFF + off) = pbh[t];
        *reinterpret_cast<uint4*>(stage + BLO_OFF + off) = pbl[t];
    }
}

__device__ __forceinline__ void compute_chunk(const char* stage, int m0, int nb,
                                              int lane, float d[4][4]) {
    const __nv_bfloat16* Ah = reinterpret_cast<const __nv_bfloat16*>(stage + AHI_OFF);
    const __nv_bfloat16* Al = reinterpret_cast<const __nv_bfloat16*>(stage + ALO_OFF);
    const __nv_bfloat16* Bh = reinterpret_cast<const __nv_bfloat16*>(stage + BHI_OFF);
    const __nv_bfloat16* Bl = reinterpret_cast<const __nv_bfloat16*>(stage + BLO_OFF);
    int g = lane >> 2, tg2 = (lane & 3) * 2;
#pragma unroll
    for (int ks = 0; ks < CHUNK / 16; ks++) {
        int k0 = ks * 16;
        int abase = (m0 + g) * LDA + k0 + tg2;
        uint32_t ah[4], al[4];
        ah[0] = *reinterpret_cast<const uint32_t*>(Ah + abase);
        ah[1] = *reinterpret_cast<const uint32_t*>(Ah + abase + 8 * LDA);
        ah[2] = *reinterpret_cast<const uint32_t*>(Ah + abase + 8);
        ah[3] = *reinterpret_cast<const uint32_t*>(Ah + abase + 8 * LDA + 8);
        al[0] = *reinterpret_cast<const uint32_t*>(Al + abase);
        al[1] = *reinterpret_cast<const uint32_t*>(Al + abase + 8 * LDA);
        al[2] = *reinterpret_cast<const uint32_t*>(Al + abase + 8);
        al[3] = *reinterpret_cast<const uint32_t*>(Al + abase + 8 * LDA + 8);
#pragma unroll
        for (int j = 0; j < 4; j++) {
            int bbase = (nb + j * 8 + g) * LDA + k0 + tg2;
            uint32_t bh0 = *reinterpret_cast<const uint32_t*>(Bh + bbase);
            uint32_t bh1 = *reinterpret_cast<const uint32_t*>(Bh + bbase + 8);
            uint32_t bl0 = *reinterpret_cast<const uint32_t*>(Bl + bbase);
            uint32_t bl1 = *reinterpret_cast<const uint32_t*>(Bl + bbase + 8);
            mma16816(d[j], ah, bh0, bh1);
            mma16816(d[j], ah, bl0, bl1);
            mma16816(d[j], al, bh0, bh1);
        }
    }
}

// ---------------------------------------------------------------------------
// Fused persistent kernel: 128 CTAs x 512 threads.
//   warps 0-7  : producers — stream W -> M (bf16 hi/lo) chunk by chunk + c
//   warps 8-15 : consumers — split-bf16 HMMA GEMM + fused relu/U epilogue
// ---------------------------------------------------------------------------
__global__ __launch_bounds__(512, 1) void fused_kernel(const float* __restrict__ W,
                                                       const float* __restrict__ V,
                                                       const float* __restrict__ x2,
                                                       const float* __restrict__ b,
                                                       const float* __restrict__ x1,
                                                       const float* __restrict__ U,
                                                       float* __restrict__ out) {
    extern __shared__ char smem[];
    float* sx2 = reinterpret_cast<float*>(smem + SX2_OFF);
    int tid = threadIdx.x, lane = tid & 31, wid = tid >> 5;

    if (tid < 256) {
        reinterpret_cast<float4*>(sx2)[tid] = reinterpret_cast<const float4*>(x2)[tid];
    }
    __syncthreads();   // only block-wide sync; roles diverge after this

    if (wid < 8) {
        // ================= PRODUCERS =================
        int p = blockIdx.x * 8 + wid;           // 0..1023
        const float4* xx = reinterpret_cast<const float4*>(sx2);

        // --- c[k] for p < 64 (done first so it's ready long before epilogue)
        if (p < 64) {
            const float4* v = reinterpret_cast<const float4*>(V + (size_t)p * 2048 + 1024);
            float s = 0.0f;
#pragma unroll
            for (int j = 0; j < 8; j++) {
                float4 a = v[lane + j * 32];
                float4 x = xx[lane + j * 32];
                s += a.x * x.x + a.y * x.y + a.z * x.z + a.w * x.w;
            }
#pragma unroll
            for (int o = 16; o; o >>= 1) s += __shfl_xor_sync(0xFFFFFFFFu, s, o);
            if (lane == 0) {
                g_c[p] = s + b[p];
                __threadfence();
                atomicAdd(&g_cnt[8], 1);
            }
        }

        int k = p >> 4;                 // 0..63
        int dd0 = (p & 15) * 8;         // 0..120
        for (int ch = 0; ch < NUM_CHUNK; ch++) {
#pragma unroll 1
            for (int i = 0; i < 8; i += 2) {
                int d0 = ch * CHUNK + dd0 + i;
                const float4* w0 = reinterpret_cast<const float4*>(W + ((size_t)k * 1024 + d0) * 1024);
                const float4* w1 = reinterpret_cast<const float4*>(W + ((size_t)k * 1024 + d0 + 1) * 1024);
                float s0 = 0.0f, s1 = 0.0f;
#pragma unroll
                for (int j = 0; j < 8; j++) {
                    float4 a0 = __ldcs(&w0[lane + j * 32]);
                    float4 a1 = __ldcs(&w1[lane + j * 32]);
                    float4 x = xx[lane + j * 32];
                    s0 += a0.x * x.x + a0.y * x.y + a0.z * x.z + a0.w * x.w;
                    s1 += a1.x * x.x + a1.y * x.y + a1.z * x.z + a1.w * x.w;
                }
#pragma unroll
                for (int o = 16; o; o >>= 1) {
                    s0 += __shfl_xor_sync(0xFFFFFFFFu, s0, o);
                    s1 += __shfl_xor_sync(0xFFFFFFFFu, s1, o);
                }
                if (lane == 0) {
                    float m0v = s0 + V[(size_t)k * 2048 + d0];
                    float m1v = s1 + V[(size_t)k * 2048 + d0 + 1];
                    __nv_bfloat16 h0 = __float2bfloat16_rn(m0v);
                    __nv_bfloat16 h1 = __float2bfloat16_rn(m1v);
                    size_t mi = (size_t)k * 1024 + d0;
                    g_Mhi[mi] = h0;
                    g_Mhi[mi + 1] = h1;
                    g_Mlo[mi] = __float2bfloat16_rn(m0v - __bfloat162float(h0));
                    g_Mlo[mi + 1] = __float2bfloat16_rn(m1v - __bfloat162float(h1));
                }
            }
            __threadfence();
            if (lane == 0) atomicAdd(&g_cnt[ch], 1);
        }
    } else {
        // ================= CONSUMERS =================
        int ctid = tid - 256;                   // 0..255
        int cw = ctid >> 5;                     // 0..7
        int wr = cw & 3, wc = cw >> 2;
        int m0 = wr * 16, nb = wc * 32;
        int row0 = blockIdx.x * 64;
        float* red = reinterpret_cast<float*>(smem + RED_OFF);

        float d[4][4] = {};
        float4 pa[8];
        uint4 pbh[4], pbl[4];

        ldg_a(x1, row0, 0, ctid, pa);
        wait_cnt(&g_cnt[0], 1024);
        ldg_b(0, ctid, pbh, pbl);
        sts_chunk(smem + ST0, ctid, pa, pbh, pbl);
        CBAR();

        for (int ch = 0; ch < NUM_CHUNK; ch++) {
            compute_chunk(smem + ST0 + (ch & 1) * STAGE_BYTES, m0, nb, lane, d);
            if (ch < NUM_CHUNK - 1) {
                ldg_a(x1, row0, ch + 1, ctid, pa);
                wait_cnt(&g_cnt[ch + 1], 1024);
                ldg_b(ch + 1, ctid, pbh, pbl);
                sts_chunk(smem + ST0 + ((ch + 1) & 1) * STAGE_BYTES, ctid, pa, pbh, pbl);
                CBAR();
            }
        }

        // fused epilogue: relu(D + c)*U, row-reduce over 64 cols -> out (N,1)
        wait_cnt(&g_cnt[8], 64);
        int g = lane >> 2, tg2 = (lane & 3) * 2;
        float accA = 0.0f, accB = 0.0f;
#pragma unroll
        for (int j = 0; j < 4; j++) {
            int col = nb + j * 8 + tg2;
            float c0 = g_c[col], c1 = g_c[col + 1];
            float u0 = U[col], u1 = U[col + 1];
            accA += fmaxf(d[j][0] + c0, 0.0f) * u0 + fmaxf(d[j][1] + c1, 0.0f) * u1;
            accB += fmaxf(d[j][2] + c0, 0.0f) * u0 + fmaxf(d[j][3] + c1, 0.0f) * u1;
        }
        accA += __shfl_xor_sync(0xFFFFFFFFu, accA, 1);
        accA += __shfl_xor_sync(0xFFFFFFFFu, accA, 2);
        accB += __shfl_xor_sync(0xFFFFFFFFu, accB, 1);
        accB += __shfl_xor_sync(0xFFFFFFFFu, accB, 2);
        if ((lane & 3) == 0) {
            red[wc * 64 + m0 + g] = accA;
            red[wc * 64 + m0 + 8 + g] = accB;
        }
        CBAR();
        if (ctid < 64) out[row0 + ctid] = red[ctid] + red[64 + ctid];
    }
}

// ---------------------------------------------------------------------------
extern "C" void kernel_launch(void* const* d_in, const int* in_sizes, int n_in,
                              void* d_out, int out_size) {
    const float* x1 = (const float*)d_in[0];  // (8192, 1024)
    const float* x2 = (const float*)d_in[1];  // (1, 1024)
    const float* V  = (const float*)d_in[2];  // (64, 2048)
    const float* W  = (const float*)d_in[3];  // (64, 1024, 1024)
    const float* b  = (const float*)d_in[4];  // (64,)
    const float* U  = (const float*)d_in[5];  // (64, 1)
    float* out = (float*)d_out;               // (8192, 1)

    // zero chunk counters each launch (graph-capturable, no allocation)
    void* cnt_addr = nullptr;
    cudaGetSymbolAddress(&cnt_addr, g_cnt);
    cudaMemsetAsync(cnt_addr, 0, sizeof(int) * 16, 0);

    cudaFuncSetAttribute(fused_kernel, cudaFuncAttributeMaxDynamicSharedMemorySize, SMEM_TOTAL);
    fused_kernel<<<128, 512, SMEM_TOTAL>>>(W, V, x2, b, x1, U, out);
}

// round 7
// speedup vs baseline: 1.1650x; 1.1650x over previous
#include <cuda_runtime.h>
#include <cuda_bf16.h>
#include <cstdint>
#include <cstddef>

// ---------------------------------------------------------------------------
// Scratch (__device__ globals; no cudaMalloc allowed)
// ---------------------------------------------------------------------------
__device__ float g_c[64];
__device__ __align__(16) __nv_bfloat16 g_Mhi[64 * 1024];
__device__ __align__(16) __nv_bfloat16 g_Mlo[64 * 1024];
__device__ int g_cnt[16];   // [0..7]: chunk counters (target 128 CTAs), [8]: c counter (target 8)

#define NUM_CHUNK 8
#define CHUNK     128
#define LDA       136
#define AHI_OFF   0
#define ALO_OFF   17408
#define BHI_OFF   34816
#define BLO_OFF   52224
#define STAGE_BYTES 69632
#define SX2_OFF   0
#define ST0       4096
#define RED_OFF   (ST0 + 2 * STAGE_BYTES)          // 143360
#define SMEM_TOTAL (RED_OFF + 512)                  // 143872

// ---------------------------------------------------------------------------
// Sync helpers
// ---------------------------------------------------------------------------
__device__ __forceinline__ int ld_acquire(const int* p) {
    int v;
    asm volatile("ld.acquire.gpu.b32 %0, [%1];" : "=r"(v) : "l"(p) : "memory");
    return v;
}

// Called by ONE consumer warp (warp 0) only; other warps park at WBAR.
__device__ __forceinline__ void wait_cnt(const int* c, int target) {
    if ((threadIdx.x & 31) == 0) {
        while (ld_acquire(c) < target) __nanosleep(128);
    }
    __syncwarp();
}

#define CBAR() asm volatile("bar.sync 1, 256;" ::: "memory")   // consumer stage barrier
#define PBAR() asm volatile("bar.sync 2, 256;" ::: "memory")   // producer chunk barrier
#define WBAR() asm volatile("bar.sync 3, 256;" ::: "memory")   // consumer wait-release

__device__ __forceinline__ uint32_t pack_bf16x2(__nv_bfloat16 a, __nv_bfloat16 b) {
    __nv_bfloat162 t; t.x = a; t.y = b;
    return *reinterpret_cast<uint32_t*>(&t);
}

__device__ __forceinline__ void split_pair(float f0, float f1, uint32_t& h, uint32_t& l) {
    __nv_bfloat16 h0 = __float2bfloat16_rn(f0);
    __nv_bfloat16 h1 = __float2bfloat16_rn(f1);
    h = pack_bf16x2(h0, h1);
    l = pack_bf16x2(__float2bfloat16_rn(f0 - __bfloat162float(h0)),
                    __float2bfloat16_rn(f1 - __bfloat162float(h1)));
}

__device__ __forceinline__ void mma16816(float d[4], const uint32_t a[4],
                                         uint32_t b0, uint32_t b1) {
    asm volatile(
        "mma.sync.aligned.m16n8k16.row.col.f32.bf16.bf16.f32 "
        "{%0,%1,%2,%3}, {%4,%5,%6,%7}, {%8,%9}, {%0,%1,%2,%3};"
        : "+f"(d[0]), "+f"(d[1]), "+f"(d[2]), "+f"(d[3])
        : "r"(a[0]), "r"(a[1]), "r"(a[2]), "r"(a[3]), "r"(b0), "r"(b1));
}

// ---------------------------------------------------------------------------
// Consumer pieces (ctid = 0..255)
// ---------------------------------------------------------------------------
__device__ __forceinline__ void ldg_a(const float* __restrict__ x1, int row0, int ch,
                                      int ctid, float4 pa[8]) {
#pragma unroll
    for (int t = 0; t < 8; t++) {
        int g = ctid + t * 256;             // 0..2047
        int r = g >> 5;                     // row 0..63
        int c4 = (g & 31) * 4;              // col 0..124
        pa[t] = *reinterpret_cast<const float4*>(x1 + (size_t)(row0 + r) * 1024 + ch * CHUNK + c4);
    }
}

__device__ __forceinline__ void ldg_b(int ch, int ctid, uint4 pbh[4], uint4 pbl[4]) {
#pragma unroll
    for (int t = 0; t < 4; t++) {
        int g = ctid + t * 256;             // 0..1023
        int n = g >> 4;                     // k_out 0..63
        int k8 = (g & 15) * 8;              // col 0..120
        pbh[t] = *reinterpret_cast<const uint4*>(g_Mhi + (size_t)n * 1024 + ch * CHUNK + k8);
        pbl[t] = *reinterpret_cast<const uint4*>(g_Mlo + (size_t)n * 1024 + ch * CHUNK + k8);
    }
}

__device__ __forceinline__ void sts_chunk(char* stage, int ctid, const float4 pa[8],
                                          const uint4 pbh[4], const uint4 pbl[4]) {
#pragma unroll
    for (int t = 0; t < 8; t++) {
        int g = ctid + t * 256;
        int r = g >> 5;
        int c4 = (g & 31) * 4;
        uint32_t h0, l0, h1, l1;
        split_pair(pa[t].x, pa[t].y, h0, l0);
        split_pair(pa[t].z, pa[t].w, h1, l1);
        int off = (r * LDA + c4) * 2;
        *reinterpret_cast<uint2*>(stage + AHI_OFF + off) = make_uint2(h0, h1);
        *reinterpret_cast<uint2*>(stage + ALO_OFF + off) = make_uint2(l0, l1);
    }
#pragma unroll
    for (int t = 0; t < 4; t++) {
        int g = ctid + t * 256;
        int n = g >> 4;
        int k8 = (g & 15) * 8;
        int off = (n * LDA + k8) * 2;
        *reinterpret_cast<uint4*>(stage + BHI_OFF + off) = pbh[t];
        *reinterpret_cast<uint4*>(stage + BLO_OFF + off) = pbl[t];
    }
}

__device__ __forceinline__ void compute_chunk(const char* stage, int m0, int nb,
                                              int lane, float d[4][4]) {
    const __nv_bfloat16* Ah = reinterpret_cast<const __nv_bfloat16*>(stage + AHI_OFF);
    const __nv_bfloat16* Al = reinterpret_cast<const __nv_bfloat16*>(stage + ALO_OFF);
    const __nv_bfloat16* Bh = reinterpret_cast<const __nv_bfloat16*>(stage + BHI_OFF);
    const __nv_bfloat16* Bl = reinterpret_cast<const __nv_bfloat16*>(stage + BLO_OFF);
    int g = lane >> 2, tg2 = (lane & 3) * 2;
#pragma unroll
    for (int ks = 0; ks < CHUNK / 16; ks++) {
        int k0 = ks * 16;
        int abase = (m0 + g) * LDA + k0 + tg2;
        uint32_t ah[4], al[4];
        ah[0] = *reinterpret_cast<const uint32_t*>(Ah + abase);
        ah[1] = *reinterpret_cast<const uint32_t*>(Ah + abase + 8 * LDA);
        ah[2] = *reinterpret_cast<const uint32_t*>(Ah + abase + 8);
        ah[3] = *reinterpret_cast<const uint32_t*>(Ah + abase + 8 * LDA + 8);
        al[0] = *reinterpret_cast<const uint32_t*>(Al + abase);
        al[1] = *reinterpret_cast<const uint32_t*>(Al + abase + 8 * LDA);
        al[2] = *reinterpret_cast<const uint32_t*>(Al + abase + 8);
        al[3] = *reinterpret_cast<const uint32_t*>(Al + abase + 8 * LDA + 8);
#pragma unroll
        for (int j = 0; j < 4; j++) {
            int bbase = (nb + j * 8 + g) * LDA + k0 + tg2;
            uint32_t bh0 = *reinterpret_cast<const uint32_t*>(Bh + bbase);
            uint32_t bh1 = *reinterpret_cast<const uint32_t*>(Bh + bbase + 8);
            uint32_t bl0 = *reinterpret_cast<const uint32_t*>(Bl + bbase);
            uint32_t bl1 = *reinterpret_cast<const uint32_t*>(Bl + bbase + 8);
            mma16816(d[j], ah, bh0, bh1);
            mma16816(d[j], ah, bl0, bl1);
            mma16816(d[j], al, bh0, bh1);
        }
    }
}

// ---------------------------------------------------------------------------
// Fused persistent kernel: 128 CTAs x 512 threads (all resident: deadlock-safe).
//   warps 0-7  (lo-wid): consumers — split-bf16 HMMA GEMM + fused epilogue
//   warps 8-15 (hi-wid): producers — stream W -> M (bf16 hi/lo) + c
// Signaling: per-CTA aggregated RED (128/chunk), single poller warp per CTA.
// ---------------------------------------------------------------------------
__global__ __launch_bounds__(512, 1) void fused_kernel(const float* __restrict__ W,
                                                       const float* __restrict__ V,
                                                       const float* __restrict__ x2,
                                                       const float* __restrict__ b,
                                                       const float* __restrict__ x1,
                                                       const float* __restrict__ U,
                                                       float* __restrict__ out) {
    extern __shared__ char smem[];
    float* sx2 = reinterpret_cast<float*>(smem + SX2_OFF);
    int tid = threadIdx.x, lane = tid & 31, wid = tid >> 5;

    if (tid < 256) {
        reinterpret_cast<float4*>(sx2)[tid] = reinterpret_cast<const float4*>(x2)[tid];
    }
    __syncthreads();   // only block-wide sync; roles diverge after this

    if (wid >= 8) {
        // ================= PRODUCERS (hi-wid: arbiter priority) =================
        int pwid = wid - 8;
        int p = blockIdx.x * 8 + pwid;          // 0..1023
        const float4* xx = reinterpret_cast<const float4*>(sx2);

        // --- c[k]: all 8 producer warps of CTAs 0..7 (p = 0..63)
        if (p < 64) {
            const float4* v = reinterpret_cast<const float4*>(V + (size_t)p * 2048 + 1024);
            float s = 0.0f;
#pragma unroll
            for (int j = 0; j < 8; j++) {
                float4 a = v[lane + j * 32];
                float4 x = xx[lane + j * 32];
                s += a.x * x.x + a.y * x.y + a.z * x.z + a.w * x.w;
            }
#pragma unroll
            for (int o = 16; o; o >>= 1) s += __shfl_xor_sync(0xFFFFFFFFu, s, o);
            if (lane == 0) g_c[p] = s + b[p];
            __threadfence();
            PBAR();
            if (tid == 256) atomicAdd(&g_cnt[8], 1);   // target 8
        }

        int k = p >> 4;                 // 0..63
        int dd0 = (p & 15) * 8;         // 0..120
        for (int ch = 0; ch < NUM_CHUNK; ch++) {
#pragma unroll 1
            for (int i = 0; i < 8; i += 2) {
                int d0 = ch * CHUNK + dd0 + i;
                const float4* w0 = reinterpret_cast<const float4*>(W + ((size_t)k * 1024 + d0) * 1024);
                const float4* w1 = reinterpret_cast<const float4*>(W + ((size_t)k * 1024 + d0 + 1) * 1024);
                float s0 = 0.0f, s1 = 0.0f;
#pragma unroll
                for (int j = 0; j < 8; j++) {
                    float4 a0 = __ldcs(&w0[lane + j * 32]);
                    float4 a1 = __ldcs(&w1[lane + j * 32]);
                    float4 x = xx[lane + j * 32];
                    s0 += a0.x * x.x + a0.y * x.y + a0.z * x.z + a0.w * x.w;
                    s1 += a1.x * x.x + a1.y * x.y + a1.z * x.z + a1.w * x.w;
                }
#pragma unroll
                for (int o = 16; o; o >>= 1) {
                    s0 += __shfl_xor_sync(0xFFFFFFFFu, s0, o);
                    s1 += __shfl_xor_sync(0xFFFFFFFFu, s1, o);
                }
                if (lane == 0) {
                    float m0v = s0 + V[(size_t)k * 2048 + d0];
                    float m1v = s1 + V[(size_t)k * 2048 + d0 + 1];
                    __nv_bfloat16 h0 = __float2bfloat16_rn(m0v);
                    __nv_bfloat16 h1 = __float2bfloat16_rn(m1v);
                    size_t mi = (size_t)k * 1024 + d0;
                    g_Mhi[mi] = h0;
                    g_Mhi[mi + 1] = h1;
                    g_Mlo[mi] = __float2bfloat16_rn(m0v - __bfloat162float(h0));
                    g_Mlo[mi + 1] = __float2bfloat16_rn(m1v - __bfloat162float(h1));
                }
            }
            // aggregate: fence per warp, CTA producer barrier, single RED per CTA
            __threadfence();
            PBAR();
            if (tid == 256) atomicAdd(&g_cnt[ch], 1);  // target 128
        }
    } else {
        // ================= CONSUMERS (lo-wid) =================
        int ctid = tid;                         // 0..255
        int cw = ctid >> 5;                     // 0..7
        int wr = cw & 3, wc = cw >> 2;
        int m0 = wr * 16, nb = wc * 32;
        int row0 = blockIdx.x * 64;
        float* red = reinterpret_cast<float*>(smem + RED_OFF);

        float d[4][4] = {};
        float4 pa[8];
        uint4 pbh[4], pbl[4];

        ldg_a(x1, row0, 0, ctid, pa);
        if (cw == 0) wait_cnt(&g_cnt[0], 128);
        WBAR();
        ldg_b(0, ctid, pbh, pbl);
        sts_chunk(smem + ST0, ctid, pa, pbh, pbl);
        CBAR();

        for (int ch = 0; ch < NUM_CHUNK; ch++) {
            compute_chunk(smem + ST0 + (ch & 1) * STAGE_BYTES, m0, nb, lane, d);
            if (ch < NUM_CHUNK - 1) {
                ldg_a(x1, row0, ch + 1, ctid, pa);
                if (cw == 0) wait_cnt(&g_cnt[ch + 1], 128);
                WBAR();
                ldg_b(ch + 1, ctid, pbh, pbl);
                sts_chunk(smem + ST0 + ((ch + 1) & 1) * STAGE_BYTES, ctid, pa, pbh, pbl);
                CBAR();
            }
        }

        // fused epilogue: relu(D + c)*U, row-reduce over 64 cols -> out (N,1)
        if (cw == 0) wait_cnt(&g_cnt[8], 8);
        WBAR();
        int g = lane >> 2, tg2 = (lane & 3) * 2;
        float accA = 0.0f, accB = 0.0f;
#pragma unroll
        for (int j = 0; j < 4; j++) {
            int col = nb + j * 8 + tg2;
            float c0 = g_c[col], c1 = g_c[col + 1];
            float u0 = U[col], u1 = U[col + 1];
            accA += fmaxf(d[j][0] + c0, 0.0f) * u0 + fmaxf(d[j][1] + c1, 0.0f) * u1;
            accB += fmaxf(d[j][2] + c0, 0.0f) * u0 + fmaxf(d[j][3] + c1, 0.0f) * u1;
        }
        accA += __shfl_xor_sync(0xFFFFFFFFu, accA, 1);
        accA += __shfl_xor_sync(0xFFFFFFFFu, accA, 2);
        accB += __shfl_xor_sync(0xFFFFFFFFu, accB, 1);
        accB += __shfl_xor_sync(0xFFFFFFFFu, accB, 2);
        if ((lane & 3) == 0) {
            red[wc * 64 + m0 + g] = accA;
            red[wc * 64 + m0 + 8 + g] = accB;
        }
        CBAR();
        if (ctid < 64) out[row0 + ctid] = red[ctid] + red[64 + ctid];
    }
}

// ---------------------------------------------------------------------------
extern "C" void kernel_launch(void* const* d_in, const int* in_sizes, int n_in,
                              void* d_out, int out_size) {
    const float* x1 = (const float*)d_in[0];  // (8192, 1024)
    const float* x2 = (const float*)d_in[1];  // (1, 1024)
    const float* V  = (const float*)d_in[2];  // (64, 2048)
    const float* W  = (const float*)d_in[3];  // (64, 1024, 1024)
    const float* b  = (const float*)d_in[4];  // (64,)
    const float* U  = (const float*)d_in[5];  // (64, 1)
    float* out = (float*)d_out;               // (8192, 1)

    // zero counters each launch (graph-capturable, no allocation)
    void* cnt_addr = nullptr;
    cudaGetSymbolAddress(&cnt_addr, g_cnt);
    cudaMemsetAsync(cnt_addr, 0, sizeof(int) * 16, 0);

    cudaFuncSetAttribute(fused_kernel, cudaFuncAttributeMaxDynamicSharedMemorySize, SMEM_TOTAL);
    fused_kernel<<<128, 512, SMEM_TOTAL>>>(W, V, x2, b, x1, U, out);
}

// round 8
// speedup vs baseline: 1.1977x; 1.0281x over previous
#include <cuda_runtime.h>
#include <cuda_bf16.h>
#include <cstdint>
#include <cstddef>

// ---------------------------------------------------------------------------
// Scratch (__device__ globals; no cudaMalloc allowed)
// ---------------------------------------------------------------------------
__device__ float g_c[64];
__device__ __align__(16) __nv_bfloat16 g_Mhi[64 * 1024];
__device__ __align__(16) __nv_bfloat16 g_Mlo[64 * 1024];
__device__ int g_cnt[16];   // [0..7]: chunk counters (target 1024 warps), [8]: c counter (target 64)

#define NUM_CHUNK 8
#define CHUNK     128
#define LDA       136
#define AHI_OFF   0
#define ALO_OFF   17408
#define BHI_OFF   34816
#define BLO_OFF   52224
#define STAGE_BYTES 69632
#define SX2_OFF   0
#define ST0       4096
#define RED_OFF   (ST0 + 2 * STAGE_BYTES)          // 143360
#define SMEM_TOTAL (RED_OFF + 512)                  // 143872

// ---------------------------------------------------------------------------
// Sync helpers
// ---------------------------------------------------------------------------
__device__ __forceinline__ int ld_acquire(const int* p) {
    int v;
    asm volatile("ld.acquire.gpu.b32 %0, [%1];" : "=r"(v) : "l"(p) : "memory");
    return v;
}

// Called by ONE consumer warp (warp 0) only; other warps park at WBAR.
__device__ __forceinline__ void wait_cnt(const int* c, int target) {
    if ((threadIdx.x & 31) == 0) {
        while (ld_acquire(c) < target) __nanosleep(64);
    }
    __syncwarp();
}

#define CBAR() asm volatile("bar.sync 1, 256;" ::: "memory")   // consumer stage barrier
#define WBAR() asm volatile("bar.sync 3, 256;" ::: "memory")   // consumer wait-release

__device__ __forceinline__ uint32_t pack_bf16x2(__nv_bfloat16 a, __nv_bfloat16 b) {
    __nv_bfloat162 t; t.x = a; t.y = b;
    return *reinterpret_cast<uint32_t*>(&t);
}

__device__ __forceinline__ void split_pair(float f0, float f1, uint32_t& h, uint32_t& l) {
    __nv_bfloat16 h0 = __float2bfloat16_rn(f0);
    __nv_bfloat16 h1 = __float2bfloat16_rn(f1);
    h = pack_bf16x2(h0, h1);
    l = pack_bf16x2(__float2bfloat16_rn(f0 - __bfloat162float(h0)),
                    __float2bfloat16_rn(f1 - __bfloat162float(h1)));
}

__device__ __forceinline__ void mma16816(float d[4], const uint32_t a[4],
                                         uint32_t b0, uint32_t b1) {
    asm volatile(
        "mma.sync.aligned.m16n8k16.row.col.f32.bf16.bf16.f32 "
        "{%0,%1,%2,%3}, {%4,%5,%6,%7}, {%8,%9}, {%0,%1,%2,%3};"
        : "+f"(d[0]), "+f"(d[1]), "+f"(d[2]), "+f"(d[3])
        : "r"(a[0]), "r"(a[1]), "r"(a[2]), "r"(a[3]), "r"(b0), "r"(b1));
}

// ---------------------------------------------------------------------------
// Consumer pieces (ctid = 0..255)
// ---------------------------------------------------------------------------
__device__ __forceinline__ void ldg_a(const float* __restrict__ x1, int row0, int ch,
                                      int ctid, float4 pa[8]) {
#pragma unroll
    for (int t = 0; t < 8; t++) {
        int g = ctid + t * 256;             // 0..2047
        int r = g >> 5;                     // row 0..63
        int c4 = (g & 31) * 4;              // col 0..124
        pa[t] = *reinterpret_cast<const float4*>(x1 + (size_t)(row0 + r) * 1024 + ch * CHUNK + c4);
    }
}

__device__ __forceinline__ void ldg_b(int ch, int ctid, uint4 pbh[4], uint4 pbl[4]) {
#pragma unroll
    for (int t = 0; t < 4; t++) {
        int g = ctid + t * 256;             // 0..1023
        int n = g >> 4;                     // k_out 0..63
        int k8 = (g & 15) * 8;              // col 0..120
        pbh[t] = *reinterpret_cast<const uint4*>(g_Mhi + (size_t)n * 1024 + ch * CHUNK + k8);
        pbl[t] = *reinterpret_cast<const uint4*>(g_Mlo + (size_t)n * 1024 + ch * CHUNK + k8);
    }
}

__device__ __forceinline__ void sts_chunk(char* stage, int ctid, const float4 pa[8],
                                          const uint4 pbh[4], const uint4 pbl[4]) {
#pragma unroll
    for (int t = 0; t < 8; t++) {
        int g = ctid + t * 256;
        int r = g >> 5;
        int c4 = (g & 31) * 4;
        uint32_t h0, l0, h1, l1;
        split_pair(pa[t].x, pa[t].y, h0, l0);
        split_pair(pa[t].z, pa[t].w, h1, l1);
        int off = (r * LDA + c4) * 2;
        *reinterpret_cast<uint2*>(stage + AHI_OFF + off) = make_uint2(h0, h1);
        *reinterpret_cast<uint2*>(stage + ALO_OFF + off) = make_uint2(l0, l1);
    }
#pragma unroll
    for (int t = 0; t < 4; t++) {
        int g = ctid + t * 256;
        int n = g >> 4;
        int k8 = (g & 15) * 8;
        int off = (n * LDA + k8) * 2;
        *reinterpret_cast<uint4*>(stage + BHI_OFF + off) = pbh[t];
        *reinterpret_cast<uint4*>(stage + BLO_OFF + off) = pbl[t];
    }
}

__device__ __forceinline__ void compute_chunk(const char* stage, int m0, int nb,
                                              int lane, float d[4][4]) {
    const __nv_bfloat16* Ah = reinterpret_cast<const __nv_bfloat16*>(stage + AHI_OFF);
    const __nv_bfloat16* Al = reinterpret_cast<const __nv_bfloat16*>(stage + ALO_OFF);
    const __nv_bfloat16* Bh = reinterpret_cast<const __nv_bfloat16*>(stage + BHI_OFF);
    const __nv_bfloat16* Bl = reinterpret_cast<const __nv_bfloat16*>(stage + BLO_OFF);
    int g = lane >> 2, tg2 = (lane & 3) * 2;
#pragma unroll
    for (int ks = 0; ks < CHUNK / 16; ks++) {
        int k0 = ks * 16;
        int abase = (m0 + g) * LDA + k0 + tg2;
        uint32_t ah[4], al[4];
        ah[0] = *reinterpret_cast<const uint32_t*>(Ah + abase);
        ah[1] = *reinterpret_cast<const uint32_t*>(Ah + abase + 8 * LDA);
        ah[2] = *reinterpret_cast<const uint32_t*>(Ah + abase + 8);
        ah[3] = *reinterpret_cast<const uint32_t*>(Ah + abase + 8 * LDA + 8);
        al[0] = *reinterpret_cast<const uint32_t*>(Al + abase);
        al[1] = *reinterpret_cast<const uint32_t*>(Al + abase + 8 * LDA);
        al[2] = *reinterpret_cast<const uint32_t*>(Al + abase + 8);
        al[3] = *reinterpret_cast<const uint32_t*>(Al + abase + 8 * LDA + 8);
#pragma unroll
        for (int j = 0; j < 4; j++) {
            int bbase = (nb + j * 8 + g) * LDA + k0 + tg2;
            uint32_t bh0 = *reinterpret_cast<const uint32_t*>(Bh + bbase);
            uint32_t bh1 = *reinterpret_cast<const uint32_t*>(Bh + bbase + 8);
            uint32_t bl0 = *reinterpret_cast<const uint32_t*>(Bl + bbase);
            uint32_t bl1 = *reinterpret_cast<const uint32_t*>(Bl + bbase + 8);
            mma16816(d[j], ah, bh0, bh1);
            mma16816(d[j], ah, bl0, bl1);
            mma16816(d[j], al, bh0, bh1);
        }
    }
}

// ---------------------------------------------------------------------------
// Fused persistent kernel: 128 CTAs x 512 threads (all resident: deadlock-safe).
//   warps 0-7  (lo-wid): consumers — split-bf16 HMMA GEMM + fused epilogue
//   warps 8-15 (hi-wid): producers — stream W -> M (bf16 hi/lo) + c
// Producers are barrier-free: per-warp lane0 fence+RED (counters target 1024).
// Consumers: single poller warp per CTA (128 pollers chip-wide).
// ---------------------------------------------------------------------------
__global__ __launch_bounds__(512, 1) void fused_kernel(const float* __restrict__ W,
                                                       const float* __restrict__ V,
                                                       const float* __restrict__ x2,
                                                       const float* __restrict__ b,
                                                       const float* __restrict__ x1,
                                                       const float* __restrict__ U,
                                                       float* __restrict__ out) {
    extern __shared__ char smem[];
    float* sx2 = reinterpret_cast<float*>(smem + SX2_OFF);
    int tid = threadIdx.x, lane = tid & 31, wid = tid >> 5;

    if (tid < 256) {
        reinterpret_cast<float4*>(sx2)[tid] = reinterpret_cast<const float4*>(x2)[tid];
    }
    __syncthreads();   // only block-wide sync; roles diverge after this

    if (wid >= 8) {
        // ================= PRODUCERS (hi-wid: arbiter priority; NO barriers) ==========
        int pwid = wid - 8;
        int p = blockIdx.x * 8 + pwid;          // 0..1023
        const float4* xx = reinterpret_cast<const float4*>(sx2);

        // --- c[k]: producer warps of CTAs 0..7 (p = 0..63)
        if (p < 64) {
            const float4* v = reinterpret_cast<const float4*>(V + (size_t)p * 2048 + 1024);
            float s = 0.0f;
#pragma unroll
            for (int j = 0; j < 8; j++) {
                float4 a = v[lane + j * 32];
                float4 x = xx[lane + j * 32];
                s += a.x * x.x + a.y * x.y + a.z * x.z + a.w * x.w;
            }
#pragma unroll
            for (int o = 16; o; o >>= 1) s += __shfl_xor_sync(0xFFFFFFFFu, s, o);
            if (lane == 0) {
                g_c[p] = s + b[p];
                __threadfence();
                atomicAdd(&g_cnt[8], 1);        // target 64
            }
        }

        int k = p >> 4;                 // 0..63
        int dd0 = (p & 15) * 8;         // 0..120
        for (int ch = 0; ch < NUM_CHUNK; ch++) {
#pragma unroll 1
            for (int i = 0; i < 8; i += 2) {
                int d0 = ch * CHUNK + dd0 + i;
                const float4* w0 = reinterpret_cast<const float4*>(W + ((size_t)k * 1024 + d0) * 1024);
                const float4* w1 = reinterpret_cast<const float4*>(W + ((size_t)k * 1024 + d0 + 1) * 1024);
                float s0 = 0.0f, s1 = 0.0f;
#pragma unroll
                for (int j = 0; j < 8; j++) {
                    float4 a0 = __ldcs(&w0[lane + j * 32]);
                    float4 a1 = __ldcs(&w1[lane + j * 32]);
                    float4 x = xx[lane + j * 32];
                    s0 += a0.x * x.x + a0.y * x.y + a0.z * x.z + a0.w * x.w;
                    s1 += a1.x * x.x + a1.y * x.y + a1.z * x.z + a1.w * x.w;
                }
#pragma unroll
                for (int o = 16; o; o >>= 1) {
                    s0 += __shfl_xor_sync(0xFFFFFFFFu, s0, o);
                    s1 += __shfl_xor_sync(0xFFFFFFFFu, s1, o);
                }
                if (lane == 0) {
                    float m0v = s0 + V[(size_t)k * 2048 + d0];
                    float m1v = s1 + V[(size_t)k * 2048 + d0 + 1];
                    __nv_bfloat16 h0 = __float2bfloat16_rn(m0v);
                    __nv_bfloat16 h1 = __float2bfloat16_rn(m1v);
                    size_t mi = (size_t)k * 1024 + d0;
                    g_Mhi[mi] = h0;
                    g_Mhi[mi + 1] = h1;
                    g_Mlo[mi] = __float2bfloat16_rn(m0v - __bfloat162float(h0));
                    g_Mlo[mi + 1] = __float2bfloat16_rn(m1v - __bfloat162float(h1));
                }
            }
            // barrier-free per-warp signal: fence + single RED from lane 0
            if (lane == 0) {
                __threadfence();
                atomicAdd(&g_cnt[ch], 1);       // target 1024
            }
        }
    } else {
        // ================= CONSUMERS (lo-wid) =================
        int ctid = tid;                         // 0..255
        int cw = ctid >> 5;                     // 0..7
        int wr = cw & 3, wc = cw >> 2;
        int m0 = wr * 16, nb = wc * 32;
        int row0 = blockIdx.x * 64;
        float* red = reinterpret_cast<float*>(smem + RED_OFF);

        float d[4][4] = {};
        float4 pa[8];
        uint4 pbh[4], pbl[4];

        ldg_a(x1, row0, 0, ctid, pa);
        if (cw == 0) wait_cnt(&g_cnt[0], 1024);
        WBAR();
        ldg_b(0, ctid, pbh, pbl);
        sts_chunk(smem + ST0, ctid, pa, pbh, pbl);
        CBAR();

        for (int ch = 0; ch < NUM_CHUNK; ch++) {
            compute_chunk(smem + ST0 + (ch & 1) * STAGE_BYTES, m0, nb, lane, d);
            if (ch < NUM_CHUNK - 1) {
                ldg_a(x1, row0, ch + 1, ctid, pa);
                if (cw == 0) wait_cnt(&g_cnt[ch + 1], 1024);
                WBAR();
                ldg_b(ch + 1, ctid, pbh, pbl);
                sts_chunk(smem + ST0 + ((ch + 1) & 1) * STAGE_BYTES, ctid, pa, pbh, pbl);
                CBAR();
            }
        }

        // fused epilogue: relu(D + c)*U, row-reduce over 64 cols -> out (N,1)
        if (cw == 0) wait_cnt(&g_cnt[8], 64);
        WBAR();
        int g = lane >> 2, tg2 = (lane & 3) * 2;
        float accA = 0.0f, accB = 0.0f;
#pragma unroll
        for (int j = 0; j < 4; j++) {
            int col = nb + j * 8 + tg2;
            float c0 = g_c[col], c1 = g_c[col + 1];
            float u0 = U[col], u1 = U[col + 1];
            accA += fmaxf(d[j][0] + c0, 0.0f) * u0 + fmaxf(d[j][1] + c1, 0.0f) * u1;
            accB += fmaxf(d[j][2] + c0, 0.0f) * u0 + fmaxf(d[j][3] + c1, 0.0f) * u1;
        }
        accA += __shfl_xor_sync(0xFFFFFFFFu, accA, 1);
        accA += __shfl_xor_sync(0xFFFFFFFFu, accA, 2);
        accB += __shfl_xor_sync(0xFFFFFFFFu, accB, 1);
        accB += __shfl_xor_sync(0xFFFFFFFFu, accB, 2);
        if ((lane & 3) == 0) {
            red[wc * 64 + m0 + g] = accA;
            red[wc * 64 + m0 + 8 + g] = accB;
        }
        CBAR();
        if (ctid < 64) out[row0 + ctid] = red[ctid] + red[64 + ctid];
    }
}

// ---------------------------------------------------------------------------
extern "C" void kernel_launch(void* const* d_in, const int* in_sizes, int n_in,
                              void* d_out, int out_size) {
    const float* x1 = (const float*)d_in[0];  // (8192, 1024)
    const float* x2 = (const float*)d_in[1];  // (1, 1024)
    const float* V  = (const float*)d_in[2];  // (64, 2048)
    const float* W  = (const float*)d_in[3];  // (64, 1024, 1024)
    const float* b  = (const float*)d_in[4];  // (64,)
    const float* U  = (const float*)d_in[5];  // (64, 1)
    float* out = (float*)d_out;               // (8192, 1)

    // zero counters each launch (graph-capturable, no allocation)
    void* cnt_addr = nullptr;
    cudaGetSymbolAddress(&cnt_addr, g_cnt);
    cudaMemsetAsync(cnt_addr, 0, sizeof(int) * 16, 0);

    cudaFuncSetAttribute(fused_kernel, cudaFuncAttributeMaxDynamicSharedMemorySize, SMEM_TOTAL);
    fused_kernel<<<128, 512, SMEM_TOTAL>>>(W, V, x2, b, x1, U, out);
}